// round 9
// baseline (speedup 1.0000x reference)
#include <cuda_runtime.h>
#include <cstdint>

// CovarianceLayer: x [64, 4, 8192, 16] fp32 -> cov [64, 4, 16, 16] fp32
// One CTA per (b,c), 256 threads, 2 CTAs/SM. Per-warp autonomous cp.async
// pipeline (depth 4), NO __syncthreads in the main loop:
//   - each warp owns 16 rows/stage; 2 LDGSTS(16B)/lane stage them into the
//     warp's private 1KB smem slot (XOR-swizzled 16B chunks, <=2-way LDS conflicts)
//   - cp.async.wait_group 3 + __syncwarp -> read row via 4x LDS.128
//   - lanes 2r/2r+1 read the same row (smem broadcast); even lanes accumulate
//     the even-m half of the 16x16 triangle, odd lanes the odd-m half,
//     branchlessly (SEL), into 40 packed-f32x2 accumulators (80 regs).
// Loads are ALWAYS in flight (3 stages deep) -> DRAM-bound by construction.

#define T_DIM    8192
#define M_DIM    16
#define NTHREADS 256
#define NU       40        // f32x2 units per parity half: 36 triangle + 4 column-sum
#define DEPTH    4         // cp.async pipeline stages
#define STAGE_B  1024      // bytes per warp per stage (16 rows x 64B)
#define NSTAGES  64        // 8192 rows / (8 warps * 16 rows)

typedef unsigned long long ull;

__device__ __forceinline__ void fma2(ull& d, ull a, ull b) {
    asm("fma.rn.f32x2 %0, %1, %2, %0;" : "+l"(d) : "l"(a), "l"(b));
}
__device__ __forceinline__ void add2(ull& d, ull a) {
    asm("add.rn.f32x2 %0, %1, %0;" : "+l"(d) : "l"(a));
}
__device__ __forceinline__ float2 u2f(ull u) {
    float2 f; asm("mov.b64 {%0,%1}, %2;" : "=f"(f.x), "=f"(f.y) : "l"(u)); return f;
}
__device__ __forceinline__ ull f2u(float lo, float hi) {
    ull u; asm("mov.b64 %0, {%1,%2};" : "=l"(u) : "f"(lo), "f"(hi)); return u;
}

__host__ __device__ __forceinline__ int unit_base(int a) { return 8 * a - a * (a - 1) / 2; }

__device__ __forceinline__ void cp16(uint32_t dst, const void* src) {
    asm volatile("cp.async.cg.shared.global [%0], [%1], 16;"
                 :: "r"(dst), "l"(src) : "memory");
}
__device__ __forceinline__ void cp_commit() {
    asm volatile("cp.async.commit_group;" ::: "memory");
}
__device__ __forceinline__ void cp_wait3() {
    asm volatile("cp.async.wait_group 3;" ::: "memory");
}
__device__ __forceinline__ void lds128(uint32_t addr, ull& a, ull& b) {
    uint32_t r0, r1, r2, r3;
    asm volatile("ld.shared.v4.b32 {%0,%1,%2,%3}, [%4];"
                 : "=r"(r0), "=r"(r1), "=r"(r2), "=r"(r3) : "r"(addr));
    asm("mov.b64 %0, {%1,%2};" : "=l"(a) : "r"(r0), "r"(r1));
    asm("mov.b64 %0, {%1,%2};" : "=l"(b) : "r"(r2), "r"(r3));
}

// Branchless parity accumulate (same numerics as R8).
__device__ __forceinline__ void accum_row(ull acc[NU], const ull v[8], bool odd) {
    #pragma unroll
    for (int a = 0; a < 8; a++) {            // m = 2a + parity
        float2 c = u2f(v[a]);
        const float vm = odd ? c.y : c.x;    // FSEL
        const ull bm = f2u(vm, vm);
        #pragma unroll
        for (int j = a; j < 8; j++)
            fma2(acc[unit_base(a) + j - a], bm, v[j]);
    }
    #pragma unroll
    for (int j = 0; j < 4; j++)
        add2(acc[36 + j], odd ? v[4 + j] : v[j]);
}

__global__ void __launch_bounds__(NTHREADS, 2)
cov_kernel(const float* __restrict__ x, float* __restrict__ out)
{
    __shared__ __align__(16) unsigned char sbuf[8 * DEPTH * STAGE_B];  // 32 KB
    __shared__ float red[8][4 * NU];
    __shared__ float tot[4 * NU];

    const int bc  = blockIdx.x;
    const int tid = threadIdx.x;
    const int wid = tid >> 5;
    const int lid = tid & 31;
    const bool odd = (lid & 1);
    const int r   = lid >> 1;          // this lane-pair's row within the stage
    const int rx  = r & 3;             // its chunk-swizzle key

    const uint32_t wbase = (uint32_t)__cvta_generic_to_shared(sbuf)
                         + (uint32_t)wid * (DEPTH * STAGE_B);

    // cp.async chunk assignment: chunk k (of 64 16B chunks/stage) -> row k>>2, quarter k&3
    const int k0 = lid,      rA = k0 >> 2, cA = k0 & 3;
    const int k1 = lid + 32, rB = k1 >> 2, cB = k1 & 3;
    const uint32_t dstA = (uint32_t)(rA * 64 + ((cA ^ (rA & 3)) * 16));
    const uint32_t dstB = (uint32_t)(rB * 64 + ((cB ^ (rB & 3)) * 16));
    const char* gbase = reinterpret_cast<const char*>(x + (size_t)bc * T_DIM * M_DIM)
                      + (size_t)wid * 16 * 64;         // this warp's rows, stage 0
    const size_t srcA = (size_t)rA * 64 + (size_t)cA * 16;
    const size_t srcB = (size_t)rB * 64 + (size_t)cB * 16;
    // stage s adds s * 128 rows * 64B = s * 8192 bytes

    ull acc[NU];
    #pragma unroll
    for (int i = 0; i < NU; i++) acc[i] = 0ULL;

    // ---- prologue: fill DEPTH stages ----
    #pragma unroll
    for (int s = 0; s < DEPTH; s++) {
        const uint32_t slot = wbase + (uint32_t)(s & (DEPTH - 1)) * STAGE_B;
        cp16(slot + dstA, gbase + (size_t)s * 8192 + srcA);
        cp16(slot + dstB, gbase + (size_t)s * 8192 + srcB);
        cp_commit();
    }

    // ---- main loop: 64 stages, warp-autonomous ----
    #pragma unroll 1
    for (int s = 0; s < NSTAGES; s++) {
        cp_wait3();
        __syncwarp();

        const uint32_t sb = wbase + (uint32_t)(s & (DEPTH - 1)) * STAGE_B + (uint32_t)(r * 64);
        ull v[8];
        lds128(sb + ((0 ^ rx) * 16), v[0], v[1]);
        lds128(sb + ((1 ^ rx) * 16), v[2], v[3]);
        lds128(sb + ((2 ^ rx) * 16), v[4], v[5]);
        lds128(sb + ((3 ^ rx) * 16), v[6], v[7]);

        __syncwarp();   // all lanes done reading this slot before refill

        if (s + DEPTH < NSTAGES) {
            const uint32_t slot = wbase + (uint32_t)((s + DEPTH) & (DEPTH - 1)) * STAGE_B;
            cp16(slot + dstA, gbase + (size_t)(s + DEPTH) * 8192 + srcA);
            cp16(slot + dstB, gbase + (size_t)(s + DEPTH) * 8192 + srcB);
        }
        cp_commit();     // empty group in the tail keeps wait_group uniform

        accum_row(acc, v, odd);   // long FMA block runs while copies fly
    }

    // ---- intra-warp reduce (parity-preserving xor strides 2,4,8,16) ----
    #pragma unroll 1
    for (int i = 0; i < NU; i++) {
        float2 f = u2f(acc[i]);
        #pragma unroll
        for (int o = 2; o <= 16; o <<= 1) {
            f.x += __shfl_xor_sync(0xFFFFFFFFu, f.x, o);
            f.y += __shfl_xor_sync(0xFFFFFFFFu, f.y, o);
        }
        if (lid < 2) {   // lane0: parity-0 totals, lane1: parity-1 totals
            red[wid][lid * (2 * NU) + 2 * i]     = f.x;
            red[wid][lid * (2 * NU) + 2 * i + 1] = f.y;
        }
    }
    __syncthreads();

    if (tid < 4 * NU) {
        float s = 0.0f;
        #pragma unroll
        for (int w = 0; w < 8; w++) s += red[w][tid];
        tot[tid] = s;
    }
    __syncthreads();

    // ---- finalize: thread (m,n) ----
    {
        const int m  = tid >> 4;
        const int n  = tid & 15;
        const int mm = (m < n) ? m : n;
        const int nn = (m < n) ? n : m;
        const int H  = mm & 1;
        const int a  = mm >> 1;
        const float S = tot[H * 80 + (unit_base(a) + (nn >> 1) - a) * 2 + (nn & 1)];

        const int jm = m >> 1, jn = n >> 1;
        const float sm = tot[((jm >= 4) ? 80 : 0) + (36 + (jm & 3)) * 2 + (m & 1)];
        const float sn = tot[((jn >= 4) ? 80 : 0) + (36 + (jn & 3)) * 2 + (n & 1)];

        const float inv_T  = 1.0f / (float)T_DIM;
        const float inv_T1 = 1.0f / (float)(T_DIM - 1);
        out[(size_t)bc * 256 + tid] = (S - sm * sn * inv_T) * inv_T1;
    }
}

extern "C" void kernel_launch(void* const* d_in, const int* in_sizes, int n_in,
                              void* d_out, int out_size)
{
    const float* x = (const float*)d_in[0];
    float* out = (float*)d_out;
    cov_kernel<<<256, NTHREADS>>>(x, out);
}

// round 13
// speedup vs baseline: 1.3123x; 1.3123x over previous
#include <cuda_runtime.h>

// CovarianceLayer: x [64, 4, 8192, 16] fp32 -> cov [64, 4, 16, 16] fp32
// One CTA per (b,c), 256 threads, 2 CTAs/SM. R8 design (direct LDG, branchless
// lane-parity triangle split, 40 packed-f32x2 accumulators, depth-2 register
// prefetch) + prefetch.global.L2 ~7 stages ahead: DRAM latency is absorbed by
// unlimited-outstanding L2 prefetches; the demand LDGs become ~250-cyc L2 hits,
// which the existing depth-2 pipeline + 4 warps/SMSP fully covers.

#define T_DIM    8192
#define M_DIM    16
#define NTHREADS 256
#define NU       40   // f32x2 units per parity half: 36 triangle + 4 column-sum
#define PF_DIST  7    // prefetch lead, in 128-row stages

typedef unsigned long long ull;

__device__ __forceinline__ void fma2(ull& d, ull a, ull b) {
    asm("fma.rn.f32x2 %0, %1, %2, %0;" : "+l"(d) : "l"(a), "l"(b));
}
__device__ __forceinline__ void add2(ull& d, ull a) {
    asm("add.rn.f32x2 %0, %1, %0;" : "+l"(d) : "l"(a));
}
__device__ __forceinline__ float2 u2f(ull u) {
    float2 f; asm("mov.b64 {%0,%1}, %2;" : "=f"(f.x), "=f"(f.y) : "l"(u)); return f;
}
__device__ __forceinline__ ull f2u(float lo, float hi) {
    ull u; asm("mov.b64 %0, {%1,%2};" : "=l"(u) : "f"(lo), "f"(hi)); return u;
}
__device__ __forceinline__ void pf_l2(const void* p) {
    asm volatile("prefetch.global.L2 [%0];" :: "l"(p));
}

__host__ __device__ __forceinline__ int unit_base(int a) { return 8 * a - a * (a - 1) / 2; }

__device__ __forceinline__ void loadrow(ull v[8], const ulonglong2* __restrict__ p) {
    ulonglong2 q0 = p[0], q1 = p[1], q2 = p[2], q3 = p[3];   // 4x LDG.128 (convergent)
    v[0] = q0.x; v[1] = q0.y; v[2] = q1.x; v[3] = q1.y;
    v[4] = q2.x; v[5] = q2.y; v[6] = q3.x; v[7] = q3.y;
}

// Branchless: `odd` is per-lane data, lowered to SEL/FSEL — no divergence.
__device__ __forceinline__ void accum_row(ull acc[NU], const ull v[8], bool odd) {
    #pragma unroll
    for (int a = 0; a < 8; a++) {            // m = 2a + parity
        float2 c = u2f(v[a]);
        const float vm = odd ? c.y : c.x;    // FSEL
        const ull bm = f2u(vm, vm);
        #pragma unroll
        for (int j = a; j < 8; j++)
            fma2(acc[unit_base(a) + j - a], bm, v[j]);   // (vm*v[2j], vm*v[2j+1])
    }
    #pragma unroll
    for (int j = 0; j < 4; j++)              // column sums: parity owns 4 pairs
        add2(acc[36 + j], odd ? v[4 + j] : v[j]);        // SELx2 + ADD2
}

__global__ void __launch_bounds__(NTHREADS, 2)
cov_kernel(const float* __restrict__ x, float* __restrict__ out)
{
    __shared__ float red[8][4 * NU];   // per-warp: [0..79]=parity0, [80..159]=parity1
    __shared__ float tot[4 * NU];      // 160 combined sums

    const int bc  = blockIdx.x;
    const int tid = threadIdx.x;
    const int wid = tid >> 5;
    const int lid = tid & 31;
    const bool odd = (lid & 1);        // parity (data-select only, never branched)
    const int lr  = lid >> 1;          // local row 0..15

    // rows handled: s*128 + wid*16 + lr, s = 0..63  (512 ull2 = one 128-row stage)
    const ulonglong2* __restrict__ rp =
        reinterpret_cast<const ulonglong2*>(x + (size_t)bc * T_DIM * M_DIM)
        + (size_t)(wid * 16 + lr) * 4;

    ull acc[NU];
    #pragma unroll
    for (int i = 0; i < NU; i++) acc[i] = 0ULL;

    // ---- L2 prefetch prologue: stages 2..PF_DIST+1 (stages 0,1 are demand-loaded now)
    #pragma unroll
    for (int s = 2; s < PF_DIST + 2; s++)
        pf_l2(rp + (size_t)s * 512);

    // ---- depth-2 register prefetch pipeline, fully convergent ----
    {
        ull A[8], B[8];
        loadrow(A, rp);                          // stage 0
        loadrow(B, rp + 512);                    // stage 1
        #pragma unroll 1
        for (int s = 0; s < 64; s += 2) {
            accum_row(acc, A, odd);
            if (s + 2 < 64) loadrow(A, rp + (size_t)(s + 2) * 512);
            if (s + PF_DIST + 2 < 64) pf_l2(rp + (size_t)(s + PF_DIST + 2) * 512);
            accum_row(acc, B, odd);
            if (s + 3 < 64) loadrow(B, rp + (size_t)(s + 3) * 512);
            if (s + PF_DIST + 3 < 64) pf_l2(rp + (size_t)(s + PF_DIST + 3) * 512);
        }
    }

    // ---- intra-warp reduce (parity-preserving xor strides 2,4,8,16) ----
    #pragma unroll 1
    for (int i = 0; i < NU; i++) {
        float2 f = u2f(acc[i]);
        #pragma unroll
        for (int o = 2; o <= 16; o <<= 1) {
            f.x += __shfl_xor_sync(0xFFFFFFFFu, f.x, o);
            f.y += __shfl_xor_sync(0xFFFFFFFFu, f.y, o);
        }
        // lane 0 holds parity-0 totals, lane 1 holds parity-1 totals
        if (lid < 2) {
            red[wid][lid * (2 * NU) + 2 * i]     = f.x;
            red[wid][lid * (2 * NU) + 2 * i + 1] = f.y;
        }
    }
    __syncthreads();

    // combine 8 warps: tot[p*80 + unit*2 + elem]
    if (tid < 4 * NU) {
        float s = 0.0f;
        #pragma unroll
        for (int w = 0; w < 8; w++) s += red[w][tid];
        tot[tid] = s;
    }
    __syncthreads();

    // ---- finalize: thread (m,n) ----
    {
        const int m  = tid >> 4;
        const int n  = tid & 15;
        const int mm = (m < n) ? m : n;
        const int nn = (m < n) ? n : m;
        const int H  = mm & 1;
        const int a  = mm >> 1;
        const float S = tot[H * 80 + (unit_base(a) + (nn >> 1) - a) * 2 + (nn & 1)];

        const int jm = m >> 1, jn = n >> 1;
        const float sm = tot[((jm >= 4) ? 80 : 0) + (36 + (jm & 3)) * 2 + (m & 1)];
        const float sn = tot[((jn >= 4) ? 80 : 0) + (36 + (jn & 3)) * 2 + (n & 1)];

        const float inv_T  = 1.0f / (float)T_DIM;
        const float inv_T1 = 1.0f / (float)(T_DIM - 1);
        out[(size_t)bc * 256 + tid] = (S - sm * sn * inv_T) * inv_T1;
    }
}

extern "C" void kernel_launch(void* const* d_in, const int* in_sizes, int n_in,
                              void* d_out, int out_size)
{
    const float* x = (const float*)d_in[0];
    float* out = (float*)d_out;
    cov_kernel<<<256, NTHREADS>>>(x, out);
}

// round 15
// speedup vs baseline: 1.3943x; 1.0625x over previous
#include <cuda_runtime.h>
#include <cstdint>

// CovarianceLayer: x [64, 4, 8192, 16] fp32 -> cov [64, 4, 16, 16] fp32
// One CTA per (b,c), 256 threads, 2 CTAs/SM. Warp-autonomous smem staging to
// fix L1 wavefront amplification: the old duplicate-row LDG pattern visited
// every 128B line 4x (lanes at 64B stride). Now each warp per stage:
//   2 coalesced LDG.128 (512B contiguous) -> regs -> 2 STS.128 into a
//   warp-private 1280B buffer (row pitch 80B => conflict-free LDS), then each
//   lane-pair re-reads its row via 4 LDS.128 (broadcast across the pair).
// Double-buffered, __syncwarp only (no CTA barriers). Branchless parity
// accumulate into 40 packed-f32x2 registers. L2 prefetch 4 stages ahead.

#define T_DIM    8192
#define M_DIM    16
#define NTHREADS 256
#define NU       40        // f32x2 units per parity half: 36 triangle + 4 column-sum
#define NSTAGES  64        // 8192 rows / (8 warps * 16 rows)
#define PITCH    80        // bytes per row in smem (16B-aligned, conflict-free)
#define STAGE_B  (16 * PITCH)   // 1280 B per warp per stage
#define PF_DIST  4         // L2 prefetch lead, in stages

typedef unsigned long long ull;

__device__ __forceinline__ void fma2(ull& d, ull a, ull b) {
    asm("fma.rn.f32x2 %0, %1, %2, %0;" : "+l"(d) : "l"(a), "l"(b));
}
__device__ __forceinline__ void add2(ull& d, ull a) {
    asm("add.rn.f32x2 %0, %1, %0;" : "+l"(d) : "l"(a));
}
__device__ __forceinline__ float2 u2f(ull u) {
    float2 f; asm("mov.b64 {%0,%1}, %2;" : "=f"(f.x), "=f"(f.y) : "l"(u)); return f;
}
__device__ __forceinline__ ull f2u(float lo, float hi) {
    ull u; asm("mov.b64 %0, {%1,%2};" : "=l"(u) : "f"(lo), "f"(hi)); return u;
}
__device__ __forceinline__ void pf_l2(const void* p) {
    asm volatile("prefetch.global.L2 [%0];" :: "l"(p));
}
__device__ __forceinline__ void sts16(uint32_t addr, ulonglong2 v) {
    asm volatile("st.shared.v2.u64 [%0], {%1,%2};" :: "r"(addr), "l"(v.x), "l"(v.y) : "memory");
}
__device__ __forceinline__ void lds16(uint32_t addr, ull& a, ull& b) {
    asm volatile("ld.shared.v2.u64 {%0,%1}, [%2];" : "=l"(a), "=l"(b) : "r"(addr));
}

__host__ __device__ __forceinline__ int unit_base(int a) { return 8 * a - a * (a - 1) / 2; }

// Branchless: `odd` is per-lane data, lowered to SEL/FSEL — no divergence.
__device__ __forceinline__ void accum_row(ull acc[NU], const ull v[8], bool odd) {
    #pragma unroll
    for (int a = 0; a < 8; a++) {            // m = 2a + parity
        float2 c = u2f(v[a]);
        const float vm = odd ? c.y : c.x;    // FSEL
        const ull bm = f2u(vm, vm);
        #pragma unroll
        for (int j = a; j < 8; j++)
            fma2(acc[unit_base(a) + j - a], bm, v[j]);   // (vm*v[2j], vm*v[2j+1])
    }
    #pragma unroll
    for (int j = 0; j < 4; j++)              // column sums: parity owns 4 pairs
        add2(acc[36 + j], odd ? v[4 + j] : v[j]);        // SELx2 + ADD2
}

__global__ void __launch_bounds__(NTHREADS, 2)
cov_kernel(const float* __restrict__ x, float* __restrict__ out)
{
    __shared__ __align__(16) unsigned char sbuf[8 * 2 * STAGE_B];  // 20 KB
    __shared__ float red[8][4 * NU];
    __shared__ float tot[4 * NU];

    const int bc  = blockIdx.x;
    const int tid = threadIdx.x;
    const int wid = tid >> 5;
    const int lid = tid & 31;
    const bool odd = (lid & 1);
    const int p   = lid >> 1;          // lane-pair -> row within stage (0..15)

    // gmem: warp w, stage s covers rows s*128 + w*16 .. +15
    // byte base for this warp: s*8192 + w*1024; lane chunk j*512 + lid*16
    const char* gw = reinterpret_cast<const char*>(x + (size_t)bc * T_DIM * M_DIM)
                   + (size_t)wid * 1024;
    const size_t off0 = (size_t)lid * 16;
    const size_t off1 = 512 + (size_t)lid * 16;

    // smem: warp-private double buffer
    const uint32_t wbuf = (uint32_t)__cvta_generic_to_shared(sbuf)
                        + (uint32_t)wid * (2 * STAGE_B);
    // STS targets: LDG j chunk = row j*8 + (lid>>2), quarter lid&3
    const uint32_t stsA = (uint32_t)(((lid >> 2)    ) * PITCH + (lid & 3) * 16);
    const uint32_t stsB = (uint32_t)(((lid >> 2) + 8) * PITCH + (lid & 3) * 16);
    // LDS base for this lane-pair's row
    const uint32_t ldsb = (uint32_t)(p * PITCH);

    ull acc[NU];
    #pragma unroll
    for (int i = 0; i < NU; i++) acc[i] = 0ULL;

    // ---- prologue ----
    ulonglong2 A0 = *reinterpret_cast<const ulonglong2*>(gw + off0);        // stage 0
    ulonglong2 A1 = *reinterpret_cast<const ulonglong2*>(gw + off1);
    sts16(wbuf + stsA, A0);
    sts16(wbuf + stsB, A1);
    A0 = *reinterpret_cast<const ulonglong2*>(gw + 8192 + off0);            // stage 1
    A1 = *reinterpret_cast<const ulonglong2*>(gw + 8192 + off1);
    #pragma unroll
    for (int s = 2; s < PF_DIST + 2; s++)
        pf_l2(gw + (size_t)s * 8192 + (lid & 7) * 128);
    __syncwarp();

    // ---- main loop: 64 stages, warp-autonomous ----
    #pragma unroll 1
    for (int s = 0; s < NSTAGES; s++) {
        const uint32_t rb = wbuf + (uint32_t)(s & 1) * STAGE_B;        // stage s
        const uint32_t wb = wbuf + (uint32_t)((s + 1) & 1) * STAGE_B;  // stage s+1

        ull v[8];
        lds16(rb + ldsb +  0, v[0], v[1]);
        lds16(rb + ldsb + 16, v[2], v[3]);
        lds16(rb + ldsb + 32, v[4], v[5]);
        lds16(rb + ldsb + 48, v[6], v[7]);

        sts16(wb + stsA, A0);                   // stage s+1 -> other buffer
        sts16(wb + stsB, A1);

        if (s + 2 < NSTAGES) {                  // load stage s+2
            A0 = *reinterpret_cast<const ulonglong2*>(gw + (size_t)(s + 2) * 8192 + off0);
            A1 = *reinterpret_cast<const ulonglong2*>(gw + (size_t)(s + 2) * 8192 + off1);
        }
        if (s + PF_DIST + 2 < NSTAGES)
            pf_l2(gw + (size_t)(s + PF_DIST + 2) * 8192 + (lid & 7) * 128);

        accum_row(acc, v, odd);                 // FMA block overlaps the LDGs

        __syncwarp();
    }

    // ---- intra-warp reduce (parity-preserving xor strides 2,4,8,16) ----
    #pragma unroll 1
    for (int i = 0; i < NU; i++) {
        float2 f = u2f(acc[i]);
        #pragma unroll
        for (int o = 2; o <= 16; o <<= 1) {
            f.x += __shfl_xor_sync(0xFFFFFFFFu, f.x, o);
            f.y += __shfl_xor_sync(0xFFFFFFFFu, f.y, o);
        }
        if (lid < 2) {   // lane0: parity-0 totals, lane1: parity-1 totals
            red[wid][lid * (2 * NU) + 2 * i]     = f.x;
            red[wid][lid * (2 * NU) + 2 * i + 1] = f.y;
        }
    }
    __syncthreads();

    if (tid < 4 * NU) {
        float s = 0.0f;
        #pragma unroll
        for (int w = 0; w < 8; w++) s += red[w][tid];
        tot[tid] = s;
    }
    __syncthreads();

    // ---- finalize: thread (m,n) ----
    {
        const int m  = tid >> 4;
        const int n  = tid & 15;
        const int mm = (m < n) ? m : n;
        const int nn = (m < n) ? n : m;
        const int H  = mm & 1;
        const int a  = mm >> 1;
        const float S = tot[H * 80 + (unit_base(a) + (nn >> 1) - a) * 2 + (nn & 1)];

        const int jm = m >> 1, jn = n >> 1;
        const float sm = tot[((jm >= 4) ? 80 : 0) + (36 + (jm & 3)) * 2 + (m & 1)];
        const float sn = tot[((jn >= 4) ? 80 : 0) + (36 + (jn & 3)) * 2 + (n & 1)];

        const float inv_T  = 1.0f / (float)T_DIM;
        const float inv_T1 = 1.0f / (float)(T_DIM - 1);
        out[(size_t)bc * 256 + tid] = (S - sm * sn * inv_T) * inv_T1;
    }
}

extern "C" void kernel_launch(void* const* d_in, const int* in_sizes, int n_in,
                              void* d_out, int out_size)
{
    const float* x = (const float*)d_in[0];
    float* out = (float*)d_out;
    cov_kernel<<<256, NTHREADS>>>(x, out);
}